// round 17
// baseline (speedup 1.0000x reference)
#include <cuda_runtime.h>
#include <cuda_bf16.h>
#include <math.h>
#include <cstdint>

#define N_NODES 100000
#define M_PAD   100096
#define N_NNZ   1000000
#define F_IN    1433
#define F_HID   128
#define F_OUT   64
#define N_POS   20000
#define N_NEG   20000
#define N_EDGES (N_POS + N_NEG)
#define EPS     1e-6f
#define T16_L0  90                 // ceil(1433/16)

// ---------------- scratch (static __device__, no allocation) ----------------
__device__ float g_x[(size_t)M_PAD * F_HID];          // zero-init: pad rows stay 0
__device__ float g_support[(size_t)M_PAD * F_HID];
__device__ float g_h[(size_t)N_NODES * F_HID];
__device__ int   g_rowptr[N_NODES + 1];
__device__ int   g_cnt[N_NODES];
__device__ int   g_bsum[128];
__device__ int   g_col[N_NNZ];
__device__ float g_val[N_NNZ];
__device__ float g_colsum[F_HID];
// B fragments pre-packed in exact mma.sync m16n8k16 per-lane layout:
// index = (t*NTILES + jg)*32 + lane  ->  uint2 {reg0, reg1}
__device__ uint2 g_Bfh[(size_t)T16_L0 * 16 * 32];
__device__ uint2 g_Bfl[(size_t)T16_L0 * 16 * 32];

#define SCAN_NB ((N_NODES + 1023) / 1024)

// ---------------- helpers ----------------
__device__ __forceinline__ void split2(float x, float y, uint32_t& hi, uint32_t& lo) {
    __nv_bfloat162 h = __float22bfloat162_rn(make_float2(x, y));
    float rx = x - __bfloat162float(h.x);
    float ry = y - __bfloat162float(h.y);
    __nv_bfloat162 l = __float22bfloat162_rn(make_float2(rx, ry));
    hi = *reinterpret_cast<uint32_t*>(&h);
    lo = *reinterpret_cast<uint32_t*>(&l);
}

__device__ __forceinline__ void mma16816(float* c, const uint32_t* a,
                                         uint32_t b0, uint32_t b1) {
    asm volatile(
        "mma.sync.aligned.m16n8k16.row.col.f32.bf16.bf16.f32 "
        "{%0,%1,%2,%3}, {%4,%5,%6,%7}, {%8,%9}, {%0,%1,%2,%3};\n"
        : "+f"(c[0]), "+f"(c[1]), "+f"(c[2]), "+f"(c[3])
        : "r"(a[0]), "r"(a[1]), "r"(a[2]), "r"(a[3]), "r"(b0), "r"(b1));
}

// ---------------- CSR build ----------------
__global__ void zero_cnt_k() {
    int i = blockIdx.x * blockDim.x + threadIdx.x;
    if (i < N_NODES) g_cnt[i] = 0;
}
__global__ void hist_k(const int* __restrict__ row) {
    int i = blockIdx.x * blockDim.x + threadIdx.x;
    if (i < N_NNZ) atomicAdd(&g_cnt[row[i]], 1);
}
__global__ void scanA_k() {
    __shared__ int sm[1024];
    int t = threadIdx.x;
    int i = blockIdx.x * 1024 + t;
    int v = (i < N_NODES) ? g_cnt[i] : 0;
    sm[t] = v;
    __syncthreads();
#pragma unroll
    for (int off = 1; off < 1024; off <<= 1) {
        int add = (t >= off) ? sm[t - off] : 0;
        __syncthreads();
        sm[t] += add;
        __syncthreads();
    }
    if (i < N_NODES) g_rowptr[i] = sm[t] - v;
    if (t == 1023) g_bsum[blockIdx.x] = sm[1023];
}
__global__ void scanB_k() {
    if (threadIdx.x == 0) {
        int run = 0;
        for (int b = 0; b < SCAN_NB; b++) { int v = g_bsum[b]; g_bsum[b] = run; run += v; }
    }
}
__global__ void scanC_k() {
    int i = blockIdx.x * 1024 + threadIdx.x;
    if (i < N_NODES) {
        int v = g_rowptr[i] + g_bsum[blockIdx.x];
        g_rowptr[i] = v;
        g_cnt[i] = v;
    }
    if (i == 0) g_rowptr[N_NODES] = N_NNZ;
}
__global__ void scatter_k(const int* __restrict__ row, const int* __restrict__ col,
                          const float* __restrict__ val) {
    int i = blockIdx.x * blockDim.x + threadIdx.x;
    if (i < N_NNZ) {
        int r = row[i];
        int p = atomicAdd(&g_cnt[r], 1);
        g_col[p] = col[i];
        g_val[p] = val[i];
    }
}

// -------- weight pre-pack into mma B-fragment register layout, hi/lo split ----
// For chunk t, ntile jg, lane l: n = jg*8 + l/4, k = (l%4)*2 (+1, +8, +9)
__global__ void bsplit2_k(const float* __restrict__ W, int K, int NT, int T16) {
    int i = blockIdx.x * blockDim.x + threadIdx.x;
    int ntiles = NT >> 3;
    int total = T16 * ntiles * 32;
    if (i >= total) return;
    int lane = i & 31;
    int jg   = (i >> 5) % ntiles;
    int t    = i / (32 * ntiles);
    int n    = jg * 8 + (lane >> 2);
    int gk   = t * 16 + (lane & 3) * 2;

    float v0 = (gk     < K) ? W[(size_t)gk * NT + n]       : 0.f;
    float v1 = (gk + 1 < K) ? W[(size_t)(gk + 1) * NT + n] : 0.f;
    float v2 = (gk + 8 < K) ? W[(size_t)(gk + 8) * NT + n] : 0.f;
    float v3 = (gk + 9 < K) ? W[(size_t)(gk + 9) * NT + n] : 0.f;
    uint2 hi, lo;
    split2(v0, v1, hi.x, lo.x);
    split2(v2, v3, hi.y, lo.y);
    g_Bfh[i] = hi;
    g_Bfl[i] = lo;
}

// ---------------- SMEM-free fragment GEMM v2: 16 x NT warp tile --------------
// C[*, NT] = A[*, K] @ W (pre-packed B fragments), 3-pass bf16 split.
// One warp owns 16 rows x NT cols: A read exactly once, split2 work halved,
// and an 8-float raw-A prefetch pipelines chunk t+1's loads under chunk t's
// 3*NTILES MMAs. No shared memory, no syncs.
template <int NT>
__global__ __launch_bounds__(128)
void gemm_frag2_k(const float* __restrict__ A, float* __restrict__ C,
                  int K, int T, int totalTiles) {
    constexpr int NTILES = NT / 8;

    int w = blockIdx.x * 4 + (threadIdx.x >> 5);
    if (w >= totalTiles) return;
    int lane = threadIdx.x & 31;
    int rowBase = w * 16;
    int lq = lane >> 2;                    // 0..7
    int lk = (lane & 3) * 2;               // 0,2,4,6

    float acc[NTILES][4];
#pragma unroll
    for (int j = 0; j < NTILES; j++)
#pragma unroll
        for (int q = 0; q < 4; q++) acc[j][q] = 0.f;

    const float* p0 = A + (size_t)(rowBase + lq) * K;      // row lq
    const float* p1 = p0 + (size_t)8 * K;                  // row lq+8

    float ar[8];
    auto load_a = [&](int t) {
        int k0 = t * 16;
        if (k0 + 15 < K) {
            const float* q0 = p0 + k0 + lk;
            const float* q1 = p1 + k0 + lk;
            ar[0] = q0[0]; ar[1] = q0[1];
            ar[2] = q1[0]; ar[3] = q1[1];
            ar[4] = q0[8]; ar[5] = q0[9];
            ar[6] = q1[8]; ar[7] = q1[9];
        } else {
            int kc = k0 + lk;
            ar[0] = (kc     < K) ? p0[kc]     : 0.f;
            ar[1] = (kc + 1 < K) ? p0[kc + 1] : 0.f;
            ar[2] = (kc     < K) ? p1[kc]     : 0.f;
            ar[3] = (kc + 1 < K) ? p1[kc + 1] : 0.f;
            ar[4] = (kc + 8 < K) ? p0[kc + 8] : 0.f;
            ar[5] = (kc + 9 < K) ? p0[kc + 9] : 0.f;
            ar[6] = (kc + 8 < K) ? p1[kc + 8] : 0.f;
            ar[7] = (kc + 9 < K) ? p1[kc + 9] : 0.f;
        }
    };

    load_a(0);
    for (int t = 0; t < T; t++) {
        // convert staged A floats -> bf16 hi/lo fragments
        uint32_t ah[4], al[4];
        split2(ar[0], ar[1], ah[0], al[0]);
        split2(ar[2], ar[3], ah[1], al[1]);
        split2(ar[4], ar[5], ah[2], al[2]);
        split2(ar[6], ar[7], ah[3], al[3]);
        // prefetch next chunk's A while MMAs below issue
        if (t + 1 < T) load_a(t + 1);

        const uint2* bhp = g_Bfh + (size_t)t * NTILES * 32 + lane;
        const uint2* blp = g_Bfl + (size_t)t * NTILES * 32 + lane;
#pragma unroll
        for (int j = 0; j < NTILES; j++) {
            uint2 bh = __ldg(&bhp[j * 32]);
            uint2 bl = __ldg(&blp[j * 32]);
            mma16816(acc[j], al, bh.x, bh.y);
            mma16816(acc[j], ah, bl.x, bl.y);
            mma16816(acc[j], ah, bh.x, bh.y);
        }
    }

    // ---- store: thread owns (rows lq, lq+8) x (cols j*8+lk, +1) ----
    float* c0 = C + (size_t)(rowBase + lq) * NT + lk;
    float* c1 = c0 + (size_t)8 * NT;
#pragma unroll
    for (int j = 0; j < NTILES; j++) {
        *reinterpret_cast<float2*>(c0 + j * 8) = make_float2(acc[j][0], acc[j][1]);
        *reinterpret_cast<float2*>(c1 + j * 8) = make_float2(acc[j][2], acc[j][3]);
    }
}

// ---------------- SpMM (CSR) + bias + ReLU : one warp per row ----------------
template <int F>
__global__ void spmm_relu_k(const float* __restrict__ bias) {
    constexpr int VEC = F / 32;
    int w = (blockIdx.x * blockDim.x + threadIdx.x) >> 5;
    if (w >= N_NODES) return;
    int lane = threadIdx.x & 31;

    float acc[VEC];
#pragma unroll
    for (int v = 0; v < VEC; v++) acc[v] = 0.f;

    int s = g_rowptr[w], e = g_rowptr[w + 1];
    const float* base = g_support;
    for (int j = s; j < e; j++) {
        int c = __ldg(&g_col[j]);
        float vv = __ldg(&g_val[j]);
        const float* p = base + (size_t)c * F + lane * VEC;
        if (VEC == 4) {
            float4 q = *reinterpret_cast<const float4*>(p);
            acc[0] += vv * q.x; acc[1] += vv * q.y;
            acc[2] += vv * q.z; acc[3] += vv * q.w;
        } else {
            float2 q = *reinterpret_cast<const float2*>(p);
            acc[0] += vv * q.x; acc[1] += vv * q.y;
        }
    }

    float* out = g_h + (size_t)w * F + lane * VEC;
    if (VEC == 4) {
        float4 b = *reinterpret_cast<const float4*>(bias + lane * 4);
        float4 r;
        r.x = fmaxf(acc[0] + b.x, 0.f);
        r.y = fmaxf(acc[1] + b.y, 0.f);
        r.z = fmaxf(acc[2] + b.z, 0.f);
        r.w = fmaxf(acc[3] + b.w, 0.f);
        *reinterpret_cast<float4*>(out) = r;
    } else {
        float2 b = *reinterpret_cast<const float2*>(bias + lane * 2);
        float2 r;
        r.x = fmaxf(acc[0] + b.x, 0.f);
        r.y = fmaxf(acc[1] + b.y, 0.f);
        *reinterpret_cast<float2*>(out) = r;
    }
}

// ---------------- column sums ----------------
__global__ void zero_colsum_k() {
    if (threadIdx.x < F_HID) g_colsum[threadIdx.x] = 0.f;
}
template <int F>
__global__ void colsum_k() {
    int f = threadIdx.x;
    float s = 0.f;
    for (int r = blockIdx.x; r < N_NODES; r += gridDim.x)
        s += g_h[(size_t)r * F + f];
    atomicAdd(&g_colsum[f], s);
}

// ---------------- PairNorm (PN-SI) ----------------
template <int F>
__global__ void pairnorm_k() {
    constexpr int VEC = F / 32;
    int w = (blockIdx.x * blockDim.x + threadIdx.x) >> 5;
    if (w >= N_NODES) return;
    int lane = threadIdx.x & 31;

    float v[VEC];
    const float* src = g_h + (size_t)w * F + lane * VEC;
    if (VEC == 4) {
        float4 q = *reinterpret_cast<const float4*>(src);
        v[0] = q.x; v[1] = q.y; v[2] = q.z; v[3] = q.w;
    } else {
        float2 q = *reinterpret_cast<const float2*>(src);
        v[0] = q.x; v[1] = q.y;
    }
    const float invN = 1.0f / (float)N_NODES;
    float ss = 0.f;
#pragma unroll
    for (int i = 0; i < VEC; i++) {
        float m = g_colsum[lane * VEC + i] * invN;
        v[i] -= m;
        ss += v[i] * v[i];
    }
#pragma unroll
    for (int off = 16; off > 0; off >>= 1)
        ss += __shfl_xor_sync(0xFFFFFFFFu, ss, off);
    float inv = 1.0f / sqrtf(EPS + ss);

    float* dst = g_x + (size_t)w * F + lane * VEC;
    if (VEC == 4) {
        float4 r; r.x = v[0] * inv; r.y = v[1] * inv; r.z = v[2] * inv; r.w = v[3] * inv;
        *reinterpret_cast<float4*>(dst) = r;
    } else {
        float2 r; r.x = v[0] * inv; r.y = v[1] * inv;
        *reinterpret_cast<float2*>(dst) = r;
    }
}

// ---------------- decode ----------------
__global__ void decode_k(const int* __restrict__ pos, const int* __restrict__ neg,
                         float* __restrict__ out) {
    int w = (blockIdx.x * blockDim.x + threadIdx.x) >> 5;
    if (w >= N_EDGES) return;
    int lane = threadIdx.x & 31;
    int s, d;
    if (w < N_POS) { s = pos[2 * w]; d = pos[2 * w + 1]; }
    else { int e = w - N_POS; s = neg[2 * e]; d = neg[2 * e + 1]; }
    float2 a = *reinterpret_cast<const float2*>(g_x + (size_t)s * F_OUT + lane * 2);
    float2 b = *reinterpret_cast<const float2*>(g_x + (size_t)d * F_OUT + lane * 2);
    float p = a.x * b.x + a.y * b.y;
#pragma unroll
    for (int off = 16; off > 0; off >>= 1)
        p += __shfl_xor_sync(0xFFFFFFFFu, p, off);
    if (lane == 0) out[w] = 1.0f / (1.0f + expf(-p));
}

// ---------------- launch ----------------
extern "C" void kernel_launch(void* const* d_in, const int* in_sizes, int n_in,
                              void* d_out, int out_size) {
    const float* in_feature = (const float*)d_in[0];
    const int*   adj_row    = (const int*)d_in[1];
    const int*   adj_col    = (const int*)d_in[2];
    const float* adj_val    = (const float*)d_in[3];
    const int*   pos_ei     = (const int*)d_in[4];
    const int*   neg_ei     = (const int*)d_in[5];
    const float* W0 = (const float*)d_in[6];
    const float* b0 = (const float*)d_in[7];
    const float* W1 = (const float*)d_in[8];
    const float* b1 = (const float*)d_in[9];
    const float* W2 = (const float*)d_in[10];
    const float* b2 = (const float*)d_in[11];
    float* out = (float*)d_out;

    float *g_x_p, *g_support_p;
    cudaGetSymbolAddress((void**)&g_x_p, g_x);
    cudaGetSymbolAddress((void**)&g_support_p, g_support);

    const int warp_grid = (N_NODES * 32 + 255) / 256;       // 12500

    // 16-row tiles: L0 A=in_feature, 100000/16 = 6250 exactly (no row guard).
    const int t_l0 = 6250;
    // L1/L2: A = g_x padded to M_PAD: 100096/16 = 6256 (pad rows are zeros).
    const int t_l12 = M_PAD / 16;

    // launch order: the big L0 GEMM sits at index 4 for ncu's capture window
    bsplit2_k<<<(T16_L0 * 16 * 32 + 255) / 256, 256>>>(W0, F_IN, F_HID, T16_L0);          // 1
    zero_cnt_k<<<(N_NODES + 255) / 256, 256>>>();                                          // 2
    hist_k<<<(N_NNZ + 255) / 256, 256>>>(adj_row);                                         // 3
    gemm_frag2_k<F_HID><<<(t_l0 + 3) / 4, 128>>>(in_feature, g_support_p, F_IN, T16_L0, t_l0); // 4 (BIG)
    scanA_k<<<SCAN_NB, 1024>>>();                                                          // 5
    scanB_k<<<1, 32>>>();                                                                  // 6
    scanC_k<<<SCAN_NB, 1024>>>();                                                          // 7
    scatter_k<<<(N_NNZ + 255) / 256, 256>>>(adj_row, adj_col, adj_val);                    // 8

    // --- layer 0 tail ---
    spmm_relu_k<F_HID><<<warp_grid, 256>>>(b0);
    zero_colsum_k<<<1, 128>>>();
    colsum_k<F_HID><<<512, F_HID>>>();
    pairnorm_k<F_HID><<<warp_grid, 256>>>();

    // --- layer 1: g_x[*,128] @ W1[128,128] ---
    bsplit2_k<<<(8 * 16 * 32 + 255) / 256, 256>>>(W1, F_HID, F_HID, 8);
    gemm_frag2_k<F_HID><<<(t_l12 + 3) / 4, 128>>>(g_x_p, g_support_p, F_HID, 8, t_l12);
    spmm_relu_k<F_HID><<<warp_grid, 256>>>(b1);
    zero_colsum_k<<<1, 128>>>();
    colsum_k<F_HID><<<512, F_HID>>>();
    pairnorm_k<F_HID><<<warp_grid, 256>>>();

    // --- layer 2: g_x[*,128] @ W2[128,64] ---
    bsplit2_k<<<(8 * 8 * 32 + 255) / 256, 256>>>(W2, F_HID, F_OUT, 8);
    gemm_frag2_k<F_OUT><<<(t_l12 + 3) / 4, 128>>>(g_x_p, g_support_p, F_HID, 8, t_l12);
    spmm_relu_k<F_OUT><<<warp_grid, 256>>>(b2);
    zero_colsum_k<<<1, 128>>>();
    colsum_k<F_OUT><<<512, F_OUT>>>();
    pairnorm_k<F_OUT><<<warp_grid, 256>>>();

    // --- decode ---
    decode_k<<<(N_EDGES * 32 + 255) / 256, 256>>>(pos_ei, neg_ei, out);
}